// round 16
// baseline (speedup 1.0000x reference)
#include <cuda_runtime.h>
#include <cuda_fp16.h>
#include <cstdint>

#define D 64
#define MAX_NODES 50000
#define CAP 128    // per-node bucket capacity; Poisson(20) max deg ~50
#define NTILE 128
#define MAX_TILES ((MAX_NODES + NTILE - 1) / NTILE)   // 391

// Scratch (no cudaMalloc allowed). g_cnt is zero-init at module load and
// re-zeroed by the gather kernel's tail each invocation, so the fill kernel
// has no prerequisite launch.
__device__ int g_cnt[MAX_NODES];
__device__ int g_bucket[(size_t)MAX_NODES * CAP];                 // 25.6 MB
// A image: f16 row-major [node][128]: cols 0-63 = x, 64-127 = agg.
__device__ __align__(16) __half2 g_Ah[(size_t)MAX_TILES * NTILE * 64];  // 12.8 MB
// B image: f16 row-major [o][128] = [U | V] rows.
__device__ __align__(16) __half g_Bh[64 * 128];

__device__ __forceinline__ unsigned h2pack(float a, float b) {
    __half2 h = __floats2half2_rn(a, b);
    return *reinterpret_cast<unsigned*>(&h);
}

// ---------------------------------------------------------------------------
// Kernel 1: block-partitioned fill || prep. Blocks [0, fillBlocks) do the
// edge bucket fill (4 edges/thread, int4); blocks [fillBlocks, ...) do the
// B and x fp16 conversions. Separate blocks -> true co-scheduling across
// SMs without lengthening any thread's serial path.
// ---------------------------------------------------------------------------
__global__ void fill_prep_kernel(const int* __restrict__ src,
                                 const int* __restrict__ dst,
                                 const float* __restrict__ U,
                                 const float* __restrict__ V,
                                 const float* __restrict__ x,
                                 int nEdges, int nNodes, int fillBlocks) {
    if ((int)blockIdx.x < fillBlocks) {
        // ---- fill: 4 edges per thread via int4 ----
        int q = blockIdx.x * blockDim.x + threadIdx.x;
        int e0 = q << 2;
        if (e0 + 4 <= nEdges) {
            int4 s4 = __ldg(reinterpret_cast<const int4*>(src + e0));
            int4 d4 = __ldg(reinterpret_cast<const int4*>(dst + e0));
            int p0 = atomicAdd(&g_cnt[d4.x], 1);
            int p1 = atomicAdd(&g_cnt[d4.y], 1);
            int p2 = atomicAdd(&g_cnt[d4.z], 1);
            int p3 = atomicAdd(&g_cnt[d4.w], 1);
            if (p0 < CAP) g_bucket[(size_t)d4.x * CAP + p0] = s4.x;
            if (p1 < CAP) g_bucket[(size_t)d4.y * CAP + p1] = s4.y;
            if (p2 < CAP) g_bucket[(size_t)d4.z * CAP + p2] = s4.z;
            if (p3 < CAP) g_bucket[(size_t)d4.w * CAP + p3] = s4.w;
        } else if (e0 < nEdges) {
            for (int e = e0; e < nEdges; e++) {
                int d = __ldg(dst + e);
                int s = __ldg(src + e);
                int pos = atomicAdd(&g_cnt[d], 1);
                if (pos < CAP) g_bucket[(size_t)d * CAP + pos] = s;
            }
        }
    } else {
        // ---- prep: B image + x -> fp16 x-half of A image ----
        int j = (blockIdx.x - fillBlocks) * blockDim.x + threadIdx.x;
        if (j < 64 * 128) {
            int n = j >> 7, k = j & 127;
            float val = (k < 64) ? __ldg(U + n * 64 + k)
                                 : __ldg(V + n * 64 + (k - 64));
            g_Bh[n * 128 + k] = __float2half(val);
        }
        if (j < nNodes * 16) {
            int node = j >> 4, c = j & 15;
            float4 v = __ldg(reinterpret_cast<const float4*>(x) +
                             (size_t)node * 16 + c);
            uint2 p;
            p.x = h2pack(v.x, v.y);
            p.y = h2pack(v.z, v.w);
            *reinterpret_cast<uint2*>(&g_Ah[(size_t)node * 64 + 2 * c]) = p;
        }
    }
}

// ---------------------------------------------------------------------------
// Kernel 2: pull-gather over the fp16 x-image (R13 version: two nodes per
// warp, 16 lanes x uint2 = 128B row). fp32 accumulation; one fp16 round at
// the end. Tail re-zeroes g_cnt for the next invocation.
// ---------------------------------------------------------------------------
__global__ __launch_bounds__(256) void gather_kernel(int nNodes) {
    int warp = (blockIdx.x * blockDim.x + threadIdx.x) >> 5;
    int lane = threadIdx.x & 31;
    int il = lane & 15;                    // lane within half-warp
    int node = (warp << 1) | (lane >> 4);  // half-warp's node
    if (node >= nNodes) return;

    int cnt = __ldg(g_cnt + node);
    if (il == 0) g_cnt[node] = 0;          // reset for next invocation
    cnt = cnt < CAP ? cnt : CAP;
    const int* row = g_bucket + (size_t)node * CAP;

    float4 acc = make_float4(0.f, 0.f, 0.f, 0.f);
    int e = 0;
    for (; e + 8 <= cnt; e += 8) {
        int s[8];
        #pragma unroll
        for (int k = 0; k < 8; k++) s[k] = __ldg(row + e + k);
        uint2 h[8];
        #pragma unroll
        for (int k = 0; k < 8; k++)
            h[k] = *reinterpret_cast<const uint2*>(&g_Ah[(size_t)s[k] * 64 + 2 * il]);
        #pragma unroll
        for (int k = 0; k < 8; k++) {
            float2 f0 = __half22float2(*reinterpret_cast<__half2*>(&h[k].x));
            float2 f1 = __half22float2(*reinterpret_cast<__half2*>(&h[k].y));
            acc.x += f0.x; acc.y += f0.y;
            acc.z += f1.x; acc.w += f1.y;
        }
    }
    for (; e < cnt; e++) {
        int s = __ldg(row + e);
        uint2 h = *reinterpret_cast<const uint2*>(&g_Ah[(size_t)s * 64 + 2 * il]);
        float2 f0 = __half22float2(*reinterpret_cast<__half2*>(&h.x));
        float2 f1 = __half22float2(*reinterpret_cast<__half2*>(&h.y));
        acc.x += f0.x; acc.y += f0.y;
        acc.z += f1.x; acc.w += f1.y;
    }

    uint2 pa;
    pa.x = h2pack(acc.x, acc.y);
    pa.y = h2pack(acc.z, acc.w);
    *reinterpret_cast<uint2*>(&g_Ah[(size_t)node * 64 + 32 + 2 * il]) = pa;
}

// ---------------------------------------------------------------------------
// Kernel 3: HMMA GEMM + ReLU (unchanged; 10.6us measured).
// ---------------------------------------------------------------------------
#define AROW 136
#define MMA_SMEM_BYTES ((NTILE * AROW + 64 * AROW) * 2)   // 52224

__global__ __launch_bounds__(128) void mma_kernel(float* __restrict__ out,
                                                  int nNodes) {
    extern __shared__ __align__(16) unsigned char smem[];
    __half* As = reinterpret_cast<__half*>(smem);                 // 128 x 136
    __half* Bs = reinterpret_cast<__half*>(smem) + NTILE * AROW;  // 64 x 136
    uint32_t smem_u32;
    asm("{ .reg .u64 t; cvta.to.shared.u64 t, %1; cvt.u32.u64 %0, t; }"
        : "=r"(smem_u32) : "l"(smem));
    uint32_t sA = smem_u32;
    uint32_t sB = smem_u32 + NTILE * AROW * 2;

    int tid = threadIdx.x;
    int w = tid >> 5, l = tid & 31;
    int nodeBase = blockIdx.x * NTILE;

    {
        const float4* gA = reinterpret_cast<const float4*>(
            g_Ah + (size_t)blockIdx.x * NTILE * 64);
        #pragma unroll
        for (int k = 0; k < 16; k++) {
            int i4 = tid + k * 128;
            int r = i4 >> 4, c = i4 & 15;
            *reinterpret_cast<float4*>(As + r * AROW + c * 8) = gA[i4];
        }
        const float4* gB = reinterpret_cast<const float4*>(g_Bh);
        #pragma unroll
        for (int k = 0; k < 8; k++) {
            int i4 = tid + k * 128;
            int r = i4 >> 4, c = i4 & 15;
            *reinterpret_cast<float4*>(Bs + r * AROW + c * 8) = gB[i4];
        }
    }
    __syncthreads();

    int aRowInTile = (l & 7) | (l & 8);
    uint32_t aColOff = (uint32_t)(((l >> 4) & 1) * 16);
    uint32_t bAddrBase = sB + (uint32_t)((l & 7) * AROW * 2) +
                         (uint32_t)(((l >> 3) & 1) * 16);

    float acc[2][8][4];
    #pragma unroll
    for (int mt = 0; mt < 2; mt++)
        #pragma unroll
        for (int nt = 0; nt < 8; nt++)
            #pragma unroll
            for (int q = 0; q < 4; q++) acc[mt][nt][q] = 0.f;

    #pragma unroll
    for (int ks = 0; ks < 8; ks++) {
        uint32_t kByte = (uint32_t)(ks * 32);
        uint32_t bf[8][2];
        #pragma unroll
        for (int nt = 0; nt < 8; nt++) {
            uint32_t addr = bAddrBase + (uint32_t)(nt * 8 * AROW * 2) + kByte;
            asm volatile("ldmatrix.sync.aligned.m8n8.x2.shared.b16 {%0,%1}, [%2];"
                         : "=r"(bf[nt][0]), "=r"(bf[nt][1]) : "r"(addr));
        }
        #pragma unroll
        for (int mt = 0; mt < 2; mt++) {
            uint32_t a0, a1, a2, a3;
            uint32_t addr = sA +
                (uint32_t)((w * 32 + mt * 16 + aRowInTile) * AROW * 2) +
                kByte + aColOff;
            asm volatile("ldmatrix.sync.aligned.m8n8.x4.shared.b16 {%0,%1,%2,%3}, [%4];"
                         : "=r"(a0), "=r"(a1), "=r"(a2), "=r"(a3) : "r"(addr));
            #pragma unroll
            for (int nt = 0; nt < 8; nt++) {
                asm volatile(
                    "mma.sync.aligned.m16n8k16.row.col.f32.f16.f16.f32 "
                    "{%0,%1,%2,%3}, {%4,%5,%6,%7}, {%8,%9}, {%0,%1,%2,%3};"
                    : "+f"(acc[mt][nt][0]), "+f"(acc[mt][nt][1]),
                      "+f"(acc[mt][nt][2]), "+f"(acc[mt][nt][3])
                    : "r"(a0), "r"(a1), "r"(a2), "r"(a3),
                      "r"(bf[nt][0]), "r"(bf[nt][1]));
            }
        }
    }

    int q = l >> 2, qt = l & 3;
    #pragma unroll
    for (int mt = 0; mt < 2; mt++) {
        int r0 = nodeBase + w * 32 + mt * 16 + q;
        int r1 = r0 + 8;
        #pragma unroll
        for (int nt = 0; nt < 8; nt++) {
            int col = nt * 8 + qt * 2;
            if (r0 < nNodes) {
                float2 o0;
                o0.x = fmaxf(acc[mt][nt][0], 0.f);
                o0.y = fmaxf(acc[mt][nt][1], 0.f);
                *reinterpret_cast<float2*>(out + (size_t)r0 * D + col) = o0;
            }
            if (r1 < nNodes) {
                float2 o1;
                o1.x = fmaxf(acc[mt][nt][2], 0.f);
                o1.y = fmaxf(acc[mt][nt][3], 0.f);
                *reinterpret_cast<float2*>(out + (size_t)r1 * D + col) = o1;
            }
        }
    }
}

// ---------------------------------------------------------------------------
// Launch: (fill || prep) -> gather -> HMMA GEMM (3 launches, one stream).
// ---------------------------------------------------------------------------
extern "C" void kernel_launch(void* const* d_in, const int* in_sizes, int n_in,
                              void* d_out, int out_size) {
    const float* x   = (const float*)d_in[0];
    const int*   src = (const int*)d_in[1];
    const int*   dst = (const int*)d_in[2];
    const float* U   = (const float*)d_in[3];
    const float* V   = (const float*)d_in[4];
    float* out = (float*)d_out;

    int nNodes = in_sizes[0] / D;
    int nEdges = in_sizes[1];
    int nTiles = (nNodes + NTILE - 1) / NTILE;

    cudaFuncSetAttribute(mma_kernel,
                         cudaFuncAttributeMaxDynamicSharedMemorySize,
                         MMA_SMEM_BYTES);

    int fq = (nEdges + 3) / 4;
    int fillBlocks = (fq + 255) / 256;                 // 977
    int prepItems = nNodes * 16;                       // covers B too (8192 < 800K)
    int prepBlocks = (prepItems + 255) / 256;          // 3125
    fill_prep_kernel<<<fillBlocks + prepBlocks, 256>>>(src, dst, U, V, x,
                                                       nEdges, nNodes, fillBlocks);

    int gwarps = (nNodes + 1) / 2;
    int gblocks = (gwarps * 32 + 255) / 256;
    gather_kernel<<<gblocks, 256>>>(nNodes);

    mma_kernel<<<nTiles, 128, MMA_SMEM_BYTES>>>(out, nNodes);
}

// round 17
// speedup vs baseline: 1.1797x; 1.1797x over previous
#include <cuda_runtime.h>
#include <cuda_fp16.h>
#include <cstdint>

#define D 64
#define MAX_NODES 50000
#define CAP 128    // per-node bucket capacity; Poisson(20) max deg ~50
#define NTILE 128
#define MAX_TILES ((MAX_NODES + NTILE - 1) / NTILE)   // 391

// Scratch (no cudaMalloc allowed).
__device__ int g_cnt[MAX_NODES];
__device__ int g_bucket[(size_t)MAX_NODES * CAP];                 // 25.6 MB
// A image: f16 row-major [node][128]: cols 0-63 = x (prep), 64-127 = agg
// (gather). The gather READS the x-half as its fp16 source mirror.
__device__ __align__(16) __half2 g_Ah[(size_t)MAX_TILES * NTILE * 64];  // 12.8 MB
// B image: f16 row-major [o][128] = [U | V] rows.
__device__ __align__(16) __half g_Bh[64 * 128];

__device__ __forceinline__ unsigned h2pack(float a, float b) {
    __half2 h = __floats2half2_rn(a, b);
    return *reinterpret_cast<unsigned*>(&h);
}

// ---------------------------------------------------------------------------
// Kernel 1: prep (R13). Zero counters; build f16 B image; convert x into the
// x-half of the A image.
// ---------------------------------------------------------------------------
__global__ void prep_kernel(const float* __restrict__ U,
                            const float* __restrict__ V,
                            const float* __restrict__ x,
                            int nNodes) {
    int i = blockIdx.x * blockDim.x + threadIdx.x;
    if (i < nNodes) g_cnt[i] = 0;
    if (i < 64 * 128) {
        int n = i >> 7, k = i & 127;
        float val = (k < 64) ? __ldg(U + n * 64 + k) : __ldg(V + n * 64 + (k - 64));
        g_Bh[n * 128 + k] = __float2half(val);
    }
    if (i < nNodes * 16) {
        int node = i >> 4, c = i & 15;     // one float4 per thread
        float4 v = __ldg(reinterpret_cast<const float4*>(x) + (size_t)node * 16 + c);
        uint2 p;
        p.x = h2pack(v.x, v.y);
        p.y = h2pack(v.z, v.w);
        *reinterpret_cast<uint2*>(&g_Ah[(size_t)node * 64 + 2 * c]) = p;
    }
}

// ---------------------------------------------------------------------------
// Kernel 2: bucket fill (R13), 4 edges per thread via int4 loads.
// ---------------------------------------------------------------------------
__global__ void fill_buckets_kernel(const int* __restrict__ src,
                                    const int* __restrict__ dst,
                                    int nEdges) {
    int q = blockIdx.x * blockDim.x + threadIdx.x;
    int e0 = q << 2;
    if (e0 + 4 <= nEdges) {
        int4 s4 = __ldg(reinterpret_cast<const int4*>(src + e0));
        int4 d4 = __ldg(reinterpret_cast<const int4*>(dst + e0));
        int p0 = atomicAdd(&g_cnt[d4.x], 1);
        int p1 = atomicAdd(&g_cnt[d4.y], 1);
        int p2 = atomicAdd(&g_cnt[d4.z], 1);
        int p3 = atomicAdd(&g_cnt[d4.w], 1);
        if (p0 < CAP) g_bucket[(size_t)d4.x * CAP + p0] = s4.x;
        if (p1 < CAP) g_bucket[(size_t)d4.y * CAP + p1] = s4.y;
        if (p2 < CAP) g_bucket[(size_t)d4.z * CAP + p2] = s4.z;
        if (p3 < CAP) g_bucket[(size_t)d4.w * CAP + p3] = s4.w;
    } else if (e0 < nEdges) {
        for (int e = e0; e < nEdges; e++) {
            int d = __ldg(dst + e);
            int s = __ldg(src + e);
            int pos = atomicAdd(&g_cnt[d], 1);
            if (pos < CAP) g_bucket[(size_t)d * CAP + pos] = s;
        }
    }
}

// ---------------------------------------------------------------------------
// Kernel 3: pull-gather over the fp16 x-image. Two nodes per warp (16 lanes x
// uint2 = 128B row). CHANGED vs R13: indices fetched 16-at-a-time via two
// int4 broadcast loads, then 16 fully independent row loads (deep MLP, 8x
// fewer idx instructions). fp32 accumulation; fp16 round once at the end.
// ---------------------------------------------------------------------------
__global__ __launch_bounds__(256) void gather_kernel(int nNodes) {
    int warp = (blockIdx.x * blockDim.x + threadIdx.x) >> 5;
    int lane = threadIdx.x & 31;
    int il = lane & 15;                    // lane within half-warp
    int node = (warp << 1) | (lane >> 4);  // half-warp's node
    if (node >= nNodes) return;

    int cnt = __ldg(g_cnt + node);
    cnt = cnt < CAP ? cnt : CAP;
    const int4* row4 = reinterpret_cast<const int4*>(g_bucket + (size_t)node * CAP);

    float4 acc = make_float4(0.f, 0.f, 0.f, 0.f);
    int e = 0;
    for (; e + 16 <= cnt; e += 16) {
        int4 i0 = __ldg(row4 + (e >> 2) + 0);
        int4 i1 = __ldg(row4 + (e >> 2) + 1);
        int4 i2 = __ldg(row4 + (e >> 2) + 2);
        int4 i3 = __ldg(row4 + (e >> 2) + 3);
        int s[16] = {i0.x, i0.y, i0.z, i0.w, i1.x, i1.y, i1.z, i1.w,
                     i2.x, i2.y, i2.z, i2.w, i3.x, i3.y, i3.z, i3.w};
        uint2 h[16];
        #pragma unroll
        for (int k = 0; k < 16; k++)
            h[k] = *reinterpret_cast<const uint2*>(&g_Ah[(size_t)s[k] * 64 + 2 * il]);
        #pragma unroll
        for (int k = 0; k < 16; k++) {
            float2 f0 = __half22float2(*reinterpret_cast<__half2*>(&h[k].x));
            float2 f1 = __half22float2(*reinterpret_cast<__half2*>(&h[k].y));
            acc.x += f0.x; acc.y += f0.y;
            acc.z += f1.x; acc.w += f1.y;
        }
    }
    for (; e + 4 <= cnt; e += 4) {
        int4 i0 = __ldg(row4 + (e >> 2));
        int s[4] = {i0.x, i0.y, i0.z, i0.w};
        uint2 h[4];
        #pragma unroll
        for (int k = 0; k < 4; k++)
            h[k] = *reinterpret_cast<const uint2*>(&g_Ah[(size_t)s[k] * 64 + 2 * il]);
        #pragma unroll
        for (int k = 0; k < 4; k++) {
            float2 f0 = __half22float2(*reinterpret_cast<__half2*>(&h[k].x));
            float2 f1 = __half22float2(*reinterpret_cast<__half2*>(&h[k].y));
            acc.x += f0.x; acc.y += f0.y;
            acc.z += f1.x; acc.w += f1.y;
        }
    }
    for (; e < cnt; e++) {
        int s = __ldg(g_bucket + (size_t)node * CAP + e);
        uint2 h = *reinterpret_cast<const uint2*>(&g_Ah[(size_t)s * 64 + 2 * il]);
        float2 f0 = __half22float2(*reinterpret_cast<__half2*>(&h.x));
        float2 f1 = __half22float2(*reinterpret_cast<__half2*>(&h.y));
        acc.x += f0.x; acc.y += f0.y;
        acc.z += f1.x; acc.w += f1.y;
    }

    uint2 pa;
    pa.x = h2pack(acc.x, acc.y);
    pa.y = h2pack(acc.z, acc.w);
    *reinterpret_cast<uint2*>(&g_Ah[(size_t)node * 64 + 32 + 2 * il]) = pa;
}

// ---------------------------------------------------------------------------
// Kernel 4: HMMA GEMM + ReLU (unchanged; ~10.6us measured).
// ---------------------------------------------------------------------------
#define AROW 136
#define MMA_SMEM_BYTES ((NTILE * AROW + 64 * AROW) * 2)   // 52224

__global__ __launch_bounds__(128) void mma_kernel(float* __restrict__ out,
                                                  int nNodes) {
    extern __shared__ __align__(16) unsigned char smem[];
    __half* As = reinterpret_cast<__half*>(smem);                 // 128 x 136
    __half* Bs = reinterpret_cast<__half*>(smem) + NTILE * AROW;  // 64 x 136
    uint32_t smem_u32;
    asm("{ .reg .u64 t; cvta.to.shared.u64 t, %1; cvt.u32.u64 %0, t; }"
        : "=r"(smem_u32) : "l"(smem));
    uint32_t sA = smem_u32;
    uint32_t sB = smem_u32 + NTILE * AROW * 2;

    int tid = threadIdx.x;
    int w = tid >> 5, l = tid & 31;
    int nodeBase = blockIdx.x * NTILE;

    {
        const float4* gA = reinterpret_cast<const float4*>(
            g_Ah + (size_t)blockIdx.x * NTILE * 64);
        #pragma unroll
        for (int k = 0; k < 16; k++) {
            int i4 = tid + k * 128;
            int r = i4 >> 4, c = i4 & 15;
            *reinterpret_cast<float4*>(As + r * AROW + c * 8) = gA[i4];
        }
        const float4* gB = reinterpret_cast<const float4*>(g_Bh);
        #pragma unroll
        for (int k = 0; k < 8; k++) {
            int i4 = tid + k * 128;
            int r = i4 >> 4, c = i4 & 15;
            *reinterpret_cast<float4*>(Bs + r * AROW + c * 8) = gB[i4];
        }
    }
    __syncthreads();

    int aRowInTile = (l & 7) | (l & 8);
    uint32_t aColOff = (uint32_t)(((l >> 4) & 1) * 16);
    uint32_t bAddrBase = sB + (uint32_t)((l & 7) * AROW * 2) +
                         (uint32_t)(((l >> 3) & 1) * 16);

    float acc[2][8][4];
    #pragma unroll
    for (int mt = 0; mt < 2; mt++)
        #pragma unroll
        for (int nt = 0; nt < 8; nt++)
            #pragma unroll
            for (int q = 0; q < 4; q++) acc[mt][nt][q] = 0.f;

    #pragma unroll
    for (int ks = 0; ks < 8; ks++) {
        uint32_t kByte = (uint32_t)(ks * 32);
        uint32_t bf[8][2];
        #pragma unroll
        for (int nt = 0; nt < 8; nt++) {
            uint32_t addr = bAddrBase + (uint32_t)(nt * 8 * AROW * 2) + kByte;
            asm volatile("ldmatrix.sync.aligned.m8n8.x2.shared.b16 {%0,%1}, [%2];"
                         : "=r"(bf[nt][0]), "=r"(bf[nt][1]) : "r"(addr));
        }
        #pragma unroll
        for (int mt = 0; mt < 2; mt++) {
            uint32_t a0, a1, a2, a3;
            uint32_t addr = sA +
                (uint32_t)((w * 32 + mt * 16 + aRowInTile) * AROW * 2) +
                kByte + aColOff;
            asm volatile("ldmatrix.sync.aligned.m8n8.x4.shared.b16 {%0,%1,%2,%3}, [%4];"
                         : "=r"(a0), "=r"(a1), "=r"(a2), "=r"(a3) : "r"(addr));
            #pragma unroll
            for (int nt = 0; nt < 8; nt++) {
                asm volatile(
                    "mma.sync.aligned.m16n8k16.row.col.f32.f16.f16.f32 "
                    "{%0,%1,%2,%3}, {%4,%5,%6,%7}, {%8,%9}, {%0,%1,%2,%3};"
                    : "+f"(acc[mt][nt][0]), "+f"(acc[mt][nt][1]),
                      "+f"(acc[mt][nt][2]), "+f"(acc[mt][nt][3])
                    : "r"(a0), "r"(a1), "r"(a2), "r"(a3),
                      "r"(bf[nt][0]), "r"(bf[nt][1]));
            }
        }
    }

    int q = l >> 2, qt = l & 3;
    #pragma unroll
    for (int mt = 0; mt < 2; mt++) {
        int r0 = nodeBase + w * 32 + mt * 16 + q;
        int r1 = r0 + 8;
        #pragma unroll
        for (int nt = 0; nt < 8; nt++) {
            int col = nt * 8 + qt * 2;
            if (r0 < nNodes) {
                float2 o0;
                o0.x = fmaxf(acc[mt][nt][0], 0.f);
                o0.y = fmaxf(acc[mt][nt][1], 0.f);
                *reinterpret_cast<float2*>(out + (size_t)r0 * D + col) = o0;
            }
            if (r1 < nNodes) {
                float2 o1;
                o1.x = fmaxf(acc[mt][nt][2], 0.f);
                o1.y = fmaxf(acc[mt][nt][3], 0.f);
                *reinterpret_cast<float2*>(out + (size_t)r1 * D + col) = o1;
            }
        }
    }
}

// ---------------------------------------------------------------------------
// Launch: prep -> fill -> gather -> HMMA GEMM (R13 structure).
// ---------------------------------------------------------------------------
extern "C" void kernel_launch(void* const* d_in, const int* in_sizes, int n_in,
                              void* d_out, int out_size) {
    const float* x   = (const float*)d_in[0];
    const int*   src = (const int*)d_in[1];
    const int*   dst = (const int*)d_in[2];
    const float* U   = (const float*)d_in[3];
    const float* V   = (const float*)d_in[4];
    float* out = (float*)d_out;

    int nNodes = in_sizes[0] / D;
    int nEdges = in_sizes[1];
    int nTiles = (nNodes + NTILE - 1) / NTILE;

    cudaFuncSetAttribute(mma_kernel,
                         cudaFuncAttributeMaxDynamicSharedMemorySize,
                         MMA_SMEM_BYTES);

    int prepN = nNodes * 16;
    prep_kernel<<<(prepN + 255) / 256, 256>>>(U, V, x, nNodes);

    int fq = (nEdges + 3) / 4;
    fill_buckets_kernel<<<(fq + 255) / 256, 256>>>(src, dst, nEdges);

    int gwarps = (nNodes + 1) / 2;
    int gblocks = (gwarps * 32 + 255) / 256;
    gather_kernel<<<gblocks, 256>>>(nNodes);

    mma_kernel<<<nTiles, 128, MMA_SMEM_BYTES>>>(out, nNodes);
}